// round 14
// baseline (speedup 1.0000x reference)
#include <cuda_runtime.h>
#include <cuda_fp16.h>
#include <cstdint>

#define N_WG   512
#define MPAIR  256
#define NCOL   512
#define N_NODE (NCOL * MPAIR)
#define BATCH  8192

// ===========================================================================
// Packed f32x2 helpers
// ===========================================================================
typedef unsigned long long F2;
__device__ __forceinline__ F2 pk(float lo, float hi) {
    F2 r; asm("mov.b64 %0, {%1, %2};" : "=l"(r) : "f"(lo), "f"(hi)); return r;
}
__device__ __forceinline__ void un2(F2 v, float& lo, float& hi) {
    asm("mov.b64 {%0, %1}, %2;" : "=f"(lo), "=f"(hi) : "l"(v));
}
__device__ __forceinline__ F2 splat(float a) { return pk(a, a); }
__device__ __forceinline__ F2 fma2(F2 a, F2 b, F2 c) {
    F2 d; asm("fma.rn.f32x2 %0, %1, %2, %3;" : "=l"(d) : "l"(a), "l"(b), "l"(c)); return d;
}
__device__ __forceinline__ F2 mul2(F2 a, F2 b) {
    F2 d; asm("mul.rn.f32x2 %0, %1, %2;" : "=l"(d) : "l"(a), "l"(b)); return d;
}
__device__ __forceinline__ float2 cmul(float2 a, float2 b) {
    return make_float2(a.x * b.x - a.y * b.y, a.x * b.y + a.y * b.x);
}
__device__ __forceinline__ float2 cadd(float2 a, float2 b) {
    return make_float2(a.x + b.x, a.y + b.y);
}
__device__ __forceinline__ uint32_t smem_u32(const void* p) {
    uint32_t a;
    asm("{ .reg .u64 t; cvta.to.shared.u64 t, %1; cvt.u32.u64 %0, t; }" : "=r"(a) : "l"(p));
    return a;
}

// ===========================================================================
// Static scratch
// ===========================================================================
__device__ float2 g_U00[N_NODE], g_U01[N_NODE], g_U10[N_NODE], g_U11[N_NODE];
// A matrix (rows 0-511 = Re, 512-1023 = Im), m-major, single fp16
__device__ __align__(16) __half g_G[1024 * 512];
// X, [k][n] layout, single fp16
__device__ __align__(16) __half g_X[512 * 8192];

// ===========================================================================
// Kernel 1 (fused): blocks [0,4096) convert X fp32->fp16;
//                   blocks [4096,4608) build per-node 2x2 U.
// ===========================================================================
__global__ __launch_bounds__(256) void prep_kernel(
        const float4* __restrict__ X4,
        const float* __restrict__ th, const float* __restrict__ ph,
        const float* __restrict__ bse, const float* __restrict__ lse) {
    if (blockIdx.x < 4096) {
        int i = blockIdx.x * 256 + threadIdx.x;
        float4 v = X4[i];
        __half2 h0, h1;
        h0.x = __float2half_rn(v.x); h0.y = __float2half_rn(v.y);
        h1.x = __float2half_rn(v.z); h1.y = __float2half_rn(v.w);
        __half2* X2 = reinterpret_cast<__half2*>(g_X);
        X2[2 * i] = h0; X2[2 * i + 1] = h1;
        return;
    }
    int idx = (blockIdx.x - 4096) * 256 + threadIdx.x;
    int c = idx >> 8;
    int p = idx & 255;
    bool msk = ((c & 1) == 0) || (p < MPAIR - 1);

    float2 U00 = {1.f, 0.f}, U01 = {0.f, 0.f}, U10 = {0.f, 0.f}, U11 = {1.f, 0.f};
    if (msk) {
        float theta = th[idx], phi = ph[idx];
        float e0 = bse[2 * idx], e1 = bse[2 * idx + 1];
        float l0 = lse[2 * idx], l1 = lse[2 * idx + 1];
        const float KL = 0.11512925464970229f;  // ln(10)/20
        float ins0 = expf(l0 * KL), ins1 = expf(l1 * KL);
        const float PI4 = 0.7853981633974483f;
        float s0, c0, s1, c1;
        sincosf(PI4 + e0, &s0, &c0);
        sincosf(PI4 + e1, &s1, &c1);
        float2 EL, ET;
        sincosf(phi, &EL.y, &EL.x);
        sincosf(theta, &ET.y, &ET.x);
        float2 L11 = {ins0 * s0, 0.f}, L12 = {0.f, ins0 * c0}, L21 = {0.f, c0}, L22 = {s0, 0.f};
        float2 R11 = {ins1 * s1, 0.f}, R12 = {0.f, ins1 * c1}, R21 = {0.f, c1}, R22 = {s1, 0.f};
        float2 M00 = cmul(L11, cmul(EL, ET));
        float2 M10 = cmul(L12, EL);
        float2 M01 = cmul(L21, ET);
        float2 M11 = L22;
        U00 = cadd(cmul(R11, M00), cmul(R21, M10));
        U01 = cadd(cmul(R11, M01), cmul(R21, M11));
        U10 = cadd(cmul(R12, M00), cmul(R22, M10));
        U11 = cadd(cmul(R12, M01), cmul(R22, M11));
    }
    g_U00[idx] = U00; g_U01[idx] = U01; g_U10[idx] = U10; g_U11[idx] = U11;
}

// ===========================================================================
// Kernel 2: propagate identity*diag(e^{i gamma}) through mesh -> A (fp16).
// v9 = round-11 winner (256 CTAs x 2 cols, 2/SM) + LIGHT-CONE SKIP:
// basis columns {jb, jb+1} have support rows [jb-c, jb+1+c] after c mesh
// columns. Threads outside the cone have provably-zero state -> skip the U
// load AND the apply2 (exchange of zeros flows through unchanged barriers).
// Cuts L2 traffic and FMA issue by ~25% on a BW-bound kernel.
// ===========================================================================
__device__ __forceinline__ void apply2(const F2* S, F2& tr, F2& ti, F2& br, F2& bi) {
    F2 ntr = fma2(S[5],  bi, fma2(S[3], br, fma2(S[2], ti, mul2(S[0], tr))));
    F2 nti = fma2(S[4],  br, fma2(S[3], bi, fma2(S[1], tr, mul2(S[0], ti))));
    F2 nbr = fma2(S[11], bi, fma2(S[9], br, fma2(S[8], ti, mul2(S[6], tr))));
    F2 nbi = fma2(S[10], br, fma2(S[9], bi, fma2(S[7], tr, mul2(S[6], ti))));
    tr = ntr; ti = nti; br = nbr; bi = nbi;
}

__device__ __forceinline__ void store_h2(int row, int col, float a, float b) {
    __half2 h;
    h.x = __float2half_rn(a);
    h.y = __float2half_rn(b);
    *reinterpret_cast<__half2*>(&g_G[(size_t)row * 512 + col]) = h;
}

__global__ __launch_bounds__(256, 2) void build_A(const float* __restrict__ gammas) {
    int r  = threadIdx.x;
    int jb = blockIdx.x * 2;           // 2 A-columns per CTA
    int i0 = 2 * r, i1 = 2 * r + 1;
    int lane = r & 31, w = r >> 5;

    float sg0, cg0, sg1, cg1;
    sincosf(gammas[i0], &sg0, &cg0);
    sincosf(gammas[i1], &sg1, &cg1);

    int j0 = jb, j1 = jb + 1;
    F2 are = pk(i0 == j0 ? cg0 : 0.f, i0 == j1 ? cg0 : 0.f);
    F2 aim = pk(i0 == j0 ? sg0 : 0.f, i0 == j1 ? sg0 : 0.f);
    F2 bre = pk(i1 == j0 ? cg1 : 0.f, i1 == j1 ? cg1 : 0.f);
    F2 bim = pk(i1 == j0 ? sg1 : 0.f, i1 == j1 ? sg1 : 0.f);

    __shared__ F2 sEA[8][2];
    __shared__ F2 sEB[8][2];

    // Light-cone activation column: exact bound is
    //   act(c) iff c >= max(jb - 2r - 2, 2r - jb - 1); use +8 safety margin.
    int dmax = max(jb - 2 * r - 2, 2 * r - jb - 1) - 8;
    if (dmax < 0) dmax = 0;

    // prefetch column 0 coefficients (guarded)
    float2 u00, u01, u10, u11;
    if (dmax <= 0) {
        u00 = g_U00[r]; u01 = g_U01[r]; u10 = g_U10[r]; u11 = g_U11[r];
    }

    for (int c = 0; c < NCOL; c++) {
        bool act  = (c >= dmax);
        float2 p00, p01, p10, p11;
        if (c + 1 < NCOL && (c + 1) >= dmax) {
            int nidx = ((c + 1) << 8) + r;
            p00 = g_U00[nidx]; p01 = g_U01[nidx]; p10 = g_U10[nidx]; p11 = g_U11[nidx];
        }
        if ((c & 1) == 0) {
            if (act) {
                F2 S[12] = {
                    splat(u00.x), splat(u00.y), splat(-u00.y),
                    splat(u01.x), splat(u01.y), splat(-u01.y),
                    splat(u10.x), splat(u10.y), splat(-u10.y),
                    splat(u11.x), splat(u11.y), splat(-u11.y)
                };
                apply2(S, are, aim, bre, bim);
            }
        } else {
            // pair p=r couples (row 2r+1 = my b, row 2r+2 = neighbor's a)
            F2 nar = __shfl_down_sync(0xffffffffu, are, 1);
            F2 nai = __shfl_down_sync(0xffffffffu, aim, 1);
            if (lane == 0 && r > 0) {
                sEA[w][0] = are; sEA[w][1] = aim;
            }
            __syncthreads();
            if (lane == 31 && r < 255) {
                nar = sEA[w + 1][0]; nai = sEA[w + 1][1];
            }
            if (r < 255 && act) {
                F2 S[12] = {
                    splat(u00.x), splat(u00.y), splat(-u00.y),
                    splat(u01.x), splat(u01.y), splat(-u01.y),
                    splat(u10.x), splat(u10.y), splat(-u10.y),
                    splat(u11.x), splat(u11.y), splat(-u11.y)
                };
                apply2(S, bre, bim, nar, nai);
            }
            F2 up0 = __shfl_up_sync(0xffffffffu, nar, 1);
            F2 up1 = __shfl_up_sync(0xffffffffu, nai, 1);
            if (lane == 31 && r < 255) {
                sEB[w + 1][0] = nar; sEB[w + 1][1] = nai;
            }
            __syncthreads();
            if (r > 0) {
                if (lane == 0) {
                    are = sEB[w][0]; aim = sEB[w][1];
                } else {
                    are = up0; aim = up1;
                }
            }
        }
        u00 = p00; u01 = p01; u10 = p10; u11 = p11;
    }

    // emit fp16, m-major: rows [0,512)=Re, [512,1024)=Im
    {
        float x, y;
        un2(are, x, y); store_h2(i0,       jb, x, y);
        un2(aim, x, y); store_h2(512 + i0, jb, x, y);
        un2(bre, x, y); store_h2(i1,       jb, x, y);
        un2(bim, x, y); store_h2(512 + i1, jb, x, y);
    }
}

// ===========================================================================
// Kernel 3: single-pass fp16 mma.sync GEMM. out[1024][8192] = G @ X (fp32 acc).
// CTA 128x128, BK=32, 3-stage cp.async pipeline, 8 warps (32x64 each).
// K = 512 -> 16 stages.
// ===========================================================================
__device__ __forceinline__ void ldmx4(uint32_t* r, uint32_t addr) {
    asm volatile("ldmatrix.sync.aligned.m8n8.x4.shared.b16 {%0,%1,%2,%3}, [%4];"
                 : "=r"(r[0]), "=r"(r[1]), "=r"(r[2]), "=r"(r[3]) : "r"(addr));
}
__device__ __forceinline__ void ldmx4t(uint32_t* r, uint32_t addr) {
    asm volatile("ldmatrix.sync.aligned.m8n8.x4.trans.shared.b16 {%0,%1,%2,%3}, [%4];"
                 : "=r"(r[0]), "=r"(r[1]), "=r"(r[2]), "=r"(r[3]) : "r"(addr));
}
__device__ __forceinline__ void mma_f16(float* c, const uint32_t* a, uint32_t b0, uint32_t b1) {
    asm volatile("mma.sync.aligned.m16n8k16.row.col.f32.f16.f16.f32 "
                 "{%0,%1,%2,%3}, {%4,%5,%6,%7}, {%8,%9}, {%0,%1,%2,%3};"
                 : "+f"(c[0]), "+f"(c[1]), "+f"(c[2]), "+f"(c[3])
                 : "r"(a[0]), "r"(a[1]), "r"(a[2]), "r"(a[3]), "r"(b0), "r"(b1));
}

__global__ __launch_bounds__(256, 2) void mma_gemm(float* __restrict__ out) {
    __shared__ __align__(1024) char raw[3 * 16384];
    uint32_t sbase = smem_u32(raw);

    int tid = threadIdx.x;
    int lane = tid & 31, wid = tid >> 5;
    int wm = wid & 3, wn = wid >> 2;
    int bm = blockIdx.y * 128, bn = blockIdx.x * 128;

    auto issue = [&](int st, int buf) {
        int kblk = st << 5;
        uint32_t base = sbase + buf * 16384;
#pragma unroll
        for (int h = 0; h < 2; h++) {
            int cA = tid + h * 256;
            int row = cA >> 2, kc = cA & 3;
            uint32_t dA = base + row * 64 + ((kc ^ ((row >> 1) & 3)) << 4);
            const __half* sA = g_G + (size_t)(bm + row) * 512 + kblk + kc * 8;
            asm volatile("cp.async.cg.shared.global [%0], [%1], 16;" :: "r"(dA), "l"(sA));
            int cB = tid + h * 256;
            int k = cB >> 4, nch = cB & 15;
            uint32_t dB = base + 8192 + k * 256 + ((nch ^ (k & 7)) << 4);
            const __half* sB = g_X + (size_t)(kblk + k) * 8192 + bn + nch * 8;
            asm volatile("cp.async.cg.shared.global [%0], [%1], 16;" :: "r"(dB), "l"(sB));
        }
        asm volatile("cp.async.commit_group;" ::: "memory");
    };

    int grp = lane >> 3, lrow = lane & 7;
    int g1 = grp & 1, g2 = grp >> 1;
    int arow = wm * 32 + g1 * 8 + lrow;
    uint32_t aBase = arow * 64 + ((g2 ^ (lrow >> 1)) << 4);
    int bk = g1 * 8 + lrow;
    uint32_t bBase = 8192 + bk * 256 + wn * 128 + ((g2 ^ lrow) << 4);

    float acc[2][8][4];
#pragma unroll
    for (int mt = 0; mt < 2; mt++)
#pragma unroll
        for (int nj = 0; nj < 8; nj++)
#pragma unroll
            for (int q = 0; q < 4; q++) acc[mt][nj][q] = 0.f;

    issue(0, 0);
    issue(1, 1);

#pragma unroll 1
    for (int st = 0; st < 16; st++) {
        int buf = st % 3;
        if (st < 15) asm volatile("cp.async.wait_group 1;" ::: "memory");
        else         asm volatile("cp.async.wait_group 0;" ::: "memory");
        __syncthreads();
        if (st + 2 < 16) issue(st + 2, (st + 2) % 3);

        uint32_t stage = sbase + buf * 16384;
#pragma unroll
        for (int s = 0; s < 2; s++) {
            uint32_t a[2][4];
            ldmx4(a[0], (stage + aBase) ^ (s << 5));
            ldmx4(a[1], (stage + aBase + 16 * 64) ^ (s << 5));
#pragma unroll
            for (int j2 = 0; j2 < 4; j2++) {
                uint32_t b[4];
                ldmx4t(b, (stage + bBase + (s << 12)) ^ (j2 << 5));
#pragma unroll
                for (int mt = 0; mt < 2; mt++) {
                    mma_f16(acc[mt][2 * j2],     a[mt], b[0], b[1]);
                    mma_f16(acc[mt][2 * j2 + 1], a[mt], b[2], b[3]);
                }
            }
        }
    }

    int mrow = bm + wm * 32 + (lane >> 2);
    int ncol = bn + wn * 64 + (lane & 3) * 2;
#pragma unroll
    for (int mt = 0; mt < 2; mt++) {
#pragma unroll
        for (int nj = 0; nj < 8; nj++) {
            float* o = out + (size_t)(mrow + mt * 16) * 8192 + ncol + nj * 8;
            *reinterpret_cast<float2*>(o)             = make_float2(acc[mt][nj][0], acc[mt][nj][1]);
            *reinterpret_cast<float2*>(o + 8 * 8192)  = make_float2(acc[mt][nj][2], acc[mt][nj][3]);
        }
    }
}

// ===========================================================================
// Launch
// ===========================================================================
extern "C" void kernel_launch(void* const* d_in, const int* in_sizes, int n_in,
                              void* d_out, int out_size) {
    const float* x      = (const float*)d_in[0];
    const float* thetas = (const float*)d_in[1];
    const float* phis   = (const float*)d_in[2];
    const float* gammas = (const float*)d_in[3];
    const float* bse    = (const float*)d_in[4];
    const float* lse    = (const float*)d_in[5];
    (void)in_sizes; (void)n_in; (void)out_size;

    prep_kernel<<<4096 + 512, 256>>>((const float4*)x, thetas, phis, bse, lse);
    build_A<<<256, 256>>>(gammas);
    mma_gemm<<<dim3(64, 8), 256>>>((float*)d_out);
}

// round 15
// speedup vs baseline: 1.0565x; 1.0565x over previous
#include <cuda_runtime.h>
#include <cuda_fp16.h>
#include <cstdint>

#define N_WG   512
#define MPAIR  256
#define NCOL   512
#define N_NODE (NCOL * MPAIR)
#define BATCH  8192

// ===========================================================================
// Packed f32x2 helpers
// ===========================================================================
typedef unsigned long long F2;
__device__ __forceinline__ F2 pk(float lo, float hi) {
    F2 r; asm("mov.b64 %0, {%1, %2};" : "=l"(r) : "f"(lo), "f"(hi)); return r;
}
__device__ __forceinline__ void un2(F2 v, float& lo, float& hi) {
    asm("mov.b64 {%0, %1}, %2;" : "=f"(lo), "=f"(hi) : "l"(v));
}
__device__ __forceinline__ F2 splat(float a) { return pk(a, a); }
__device__ __forceinline__ F2 fma2(F2 a, F2 b, F2 c) {
    F2 d; asm("fma.rn.f32x2 %0, %1, %2, %3;" : "=l"(d) : "l"(a), "l"(b), "l"(c)); return d;
}
__device__ __forceinline__ F2 mul2(F2 a, F2 b) {
    F2 d; asm("mul.rn.f32x2 %0, %1, %2;" : "=l"(d) : "l"(a), "l"(b)); return d;
}
__device__ __forceinline__ float2 cmul(float2 a, float2 b) {
    return make_float2(a.x * b.x - a.y * b.y, a.x * b.y + a.y * b.x);
}
__device__ __forceinline__ float2 cadd(float2 a, float2 b) {
    return make_float2(a.x + b.x, a.y + b.y);
}
__device__ __forceinline__ uint32_t smem_u32(const void* p) {
    uint32_t a;
    asm("{ .reg .u64 t; cvta.to.shared.u64 t, %1; cvt.u32.u64 %0, t; }" : "=r"(a) : "l"(p));
    return a;
}

// ===========================================================================
// Static scratch
// ===========================================================================
__device__ float2 g_U00[N_NODE], g_U01[N_NODE], g_U10[N_NODE], g_U11[N_NODE];
// Final A matrix [Re;Im] m-major (1024 x 512), fp16 (input to final GEMM)
__device__ __align__(16) __half g_G[1024 * 512];
// X, [k][n] layout, fp16
__device__ __align__(16) __half g_X[512 * 8192];
// Segment-0 result S0 = T0*diag(e^ig), stacked [Re;Im]: Sstk[k][j], 1024x512, hi/lo fp16
__device__ __align__(16) __half g_Sh[1024 * 512];
__device__ __align__(16) __half g_Sl[1024 * 512];
// Segment-1 result T1 as Bstk = [[Re,-Im],[Im,Re]], m-major 1024x1024, hi/lo fp16
__device__ __align__(16) __half g_Bh[1024 * 1024];
__device__ __align__(16) __half g_Bl[1024 * 1024];

// ===========================================================================
// Kernel 1 (fused): blocks [0,4096) convert X fp32->fp16;
//                   blocks [4096,4608) build per-node 2x2 U.
// ===========================================================================
__global__ __launch_bounds__(256) void prep_kernel(
        const float4* __restrict__ X4,
        const float* __restrict__ th, const float* __restrict__ ph,
        const float* __restrict__ bse, const float* __restrict__ lse) {
    if (blockIdx.x < 4096) {
        int i = blockIdx.x * 256 + threadIdx.x;
        float4 v = X4[i];
        __half2 h0, h1;
        h0.x = __float2half_rn(v.x); h0.y = __float2half_rn(v.y);
        h1.x = __float2half_rn(v.z); h1.y = __float2half_rn(v.w);
        __half2* X2 = reinterpret_cast<__half2*>(g_X);
        X2[2 * i] = h0; X2[2 * i + 1] = h1;
        return;
    }
    int idx = (blockIdx.x - 4096) * 256 + threadIdx.x;
    int c = idx >> 8;
    int p = idx & 255;
    bool msk = ((c & 1) == 0) || (p < MPAIR - 1);

    float2 U00 = {1.f, 0.f}, U01 = {0.f, 0.f}, U10 = {0.f, 0.f}, U11 = {1.f, 0.f};
    if (msk) {
        float theta = th[idx], phi = ph[idx];
        float e0 = bse[2 * idx], e1 = bse[2 * idx + 1];
        float l0 = lse[2 * idx], l1 = lse[2 * idx + 1];
        const float KL = 0.11512925464970229f;  // ln(10)/20
        float ins0 = expf(l0 * KL), ins1 = expf(l1 * KL);
        const float PI4 = 0.7853981633974483f;
        float s0, c0, s1, c1;
        sincosf(PI4 + e0, &s0, &c0);
        sincosf(PI4 + e1, &s1, &c1);
        float2 EL, ET;
        sincosf(phi, &EL.y, &EL.x);
        sincosf(theta, &ET.y, &ET.x);
        float2 L11 = {ins0 * s0, 0.f}, L12 = {0.f, ins0 * c0}, L21 = {0.f, c0}, L22 = {s0, 0.f};
        float2 R11 = {ins1 * s1, 0.f}, R12 = {0.f, ins1 * c1}, R21 = {0.f, c1}, R22 = {s1, 0.f};
        float2 M00 = cmul(L11, cmul(EL, ET));
        float2 M10 = cmul(L12, EL);
        float2 M01 = cmul(L21, ET);
        float2 M11 = L22;
        U00 = cadd(cmul(R11, M00), cmul(R21, M10));
        U01 = cadd(cmul(R11, M01), cmul(R21, M11));
        U10 = cadd(cmul(R12, M00), cmul(R22, M10));
        U11 = cadd(cmul(R12, M01), cmul(R22, M11));
    }
    g_U00[idx] = U00; g_U01[idx] = U01; g_U10[idx] = U10; g_U11[idx] = U11;
}

// ===========================================================================
// Kernel 2: segmented propagation. 2 segments x 256 mesh columns.
// CTAs [0,128): segment 0, seed diag(e^ig)  -> writes Sstk (hi/lo fp16)
// CTAs [128,256): segment 1, seed identity  -> writes Bstk (hi/lo fp16)
// Each CTA: 4 basis columns (2 F2 packs), proven round-3/11 exchange body.
// Traffic: 256 CTAs x 2MB = 512MB L2 (half of round-11's 1GB).
// ===========================================================================
__device__ __forceinline__ void apply2(const F2* S, F2& tr, F2& ti, F2& br, F2& bi) {
    F2 ntr = fma2(S[5],  bi, fma2(S[3], br, fma2(S[2], ti, mul2(S[0], tr))));
    F2 nti = fma2(S[4],  br, fma2(S[3], bi, fma2(S[1], tr, mul2(S[0], ti))));
    F2 nbr = fma2(S[11], bi, fma2(S[9], br, fma2(S[8], ti, mul2(S[6], tr))));
    F2 nbi = fma2(S[10], br, fma2(S[9], bi, fma2(S[7], tr, mul2(S[6], ti))));
    tr = ntr; ti = nti; br = nbr; bi = nbi;
}

__device__ __forceinline__ void hl_split(float x, __half& h, __half& l) {
    h = __float2half_rn(x);
    l = __float2half_rn(x - __half2float(h));
}
// write one F2 (2 consecutive cols) to Sstk[row][col..col+1]
__device__ __forceinline__ void emitS(int row, int col, F2 v) {
    float x, y; un2(v, x, y);
    __half2 H, L;
    hl_split(x, H.x, L.x); hl_split(y, H.y, L.y);
    *reinterpret_cast<__half2*>(&g_Sh[(size_t)row * 512 + col]) = H;
    *reinterpret_cast<__half2*>(&g_Sl[(size_t)row * 512 + col]) = L;
}
// write one F2 to Bstk[row][col..col+1] (optionally negated)
__device__ __forceinline__ void emitB(int row, int col, F2 v, bool neg) {
    float x, y; un2(v, x, y);
    if (neg) { x = -x; y = -y; }
    __half2 H, L;
    hl_split(x, H.x, L.x); hl_split(y, H.y, L.y);
    *reinterpret_cast<__half2*>(&g_Bh[(size_t)row * 1024 + col]) = H;
    *reinterpret_cast<__half2*>(&g_Bl[(size_t)row * 1024 + col]) = L;
}

__global__ __launch_bounds__(256, 2) void propagate(const float* __restrict__ gammas) {
    int r   = threadIdx.x;
    int bid = blockIdx.x;
    int seg = bid >> 7;                 // 0 or 1
    int jb  = (bid & 127) * 4;          // 4 basis columns
    int cbase = seg << 8;               // global mesh column offset (0 or 256)

    int i0 = 2 * r, i1 = 2 * r + 1;
    int lane = r & 31, w = r >> 5;

    float sg0 = 0.f, cg0 = 1.f, sg1 = 0.f, cg1 = 1.f;
    if (seg == 0) {
        sincosf(gammas[i0], &sg0, &cg0);
        sincosf(gammas[i1], &sg1, &cg1);
    }

    F2 are[2], aim[2], bre[2], bim[2];
#pragma unroll
    for (int k = 0; k < 2; k++) {
        int j0 = jb + 2 * k, j1 = j0 + 1;
        are[k] = pk(i0 == j0 ? cg0 : 0.f, i0 == j1 ? cg0 : 0.f);
        aim[k] = pk(i0 == j0 ? sg0 : 0.f, i0 == j1 ? sg0 : 0.f);
        bre[k] = pk(i1 == j0 ? cg1 : 0.f, i1 == j1 ? cg1 : 0.f);
        bim[k] = pk(i1 == j0 ? sg1 : 0.f, i1 == j1 ? sg1 : 0.f);
    }

    __shared__ F2 sEA[8][4];
    __shared__ F2 sEB[8][4];

    // prefetch local column 0 (global cbase)
    int ub = (cbase << 8) + r;
    float2 u00 = g_U00[ub], u01 = g_U01[ub], u10 = g_U10[ub], u11 = g_U11[ub];

    for (int c = 0; c < 256; c++) {
        float2 p00, p01, p10, p11;
        if (c + 1 < 256) {
            int nidx = ((cbase + c + 1) << 8) + r;
            p00 = g_U00[nidx]; p01 = g_U01[nidx]; p10 = g_U10[nidx]; p11 = g_U11[nidx];
        }
        F2 S[12] = {
            splat(u00.x), splat(u00.y), splat(-u00.y),
            splat(u01.x), splat(u01.y), splat(-u01.y),
            splat(u10.x), splat(u10.y), splat(-u10.y),
            splat(u11.x), splat(u11.y), splat(-u11.y)
        };
        if ((c & 1) == 0) {          // global parity == local parity (cbase even)
#pragma unroll
            for (int k = 0; k < 2; k++)
                apply2(S, are[k], aim[k], bre[k], bim[k]);
        } else {
            F2 nar[2], nai[2];
#pragma unroll
            for (int k = 0; k < 2; k++) {
                nar[k] = __shfl_down_sync(0xffffffffu, are[k], 1);
                nai[k] = __shfl_down_sync(0xffffffffu, aim[k], 1);
            }
            if (lane == 0 && r > 0) {
                sEA[w][0] = are[0]; sEA[w][1] = are[1];
                sEA[w][2] = aim[0]; sEA[w][3] = aim[1];
            }
            __syncthreads();
            if (lane == 31 && r < 255) {
                nar[0] = sEA[w + 1][0]; nar[1] = sEA[w + 1][1];
                nai[0] = sEA[w + 1][2]; nai[1] = sEA[w + 1][3];
            }
            if (r < 255) {
#pragma unroll
                for (int k = 0; k < 2; k++)
                    apply2(S, bre[k], bim[k], nar[k], nai[k]);
            }
            F2 up0 = __shfl_up_sync(0xffffffffu, nar[0], 1);
            F2 up1 = __shfl_up_sync(0xffffffffu, nar[1], 1);
            F2 up2 = __shfl_up_sync(0xffffffffu, nai[0], 1);
            F2 up3 = __shfl_up_sync(0xffffffffu, nai[1], 1);
            if (lane == 31 && r < 255) {
                sEB[w + 1][0] = nar[0]; sEB[w + 1][1] = nar[1];
                sEB[w + 1][2] = nai[0]; sEB[w + 1][3] = nai[1];
            }
            __syncthreads();
            if (r > 0) {
                if (lane == 0) {
                    are[0] = sEB[w][0]; are[1] = sEB[w][1];
                    aim[0] = sEB[w][2]; aim[1] = sEB[w][3];
                } else {
                    are[0] = up0; are[1] = up1; aim[0] = up2; aim[1] = up3;
                }
            }
        }
        u00 = p00; u01 = p01; u10 = p10; u11 = p11;
    }

    if (seg == 0) {
        // Sstk[k][j]: rows [0,512)=Re, [512,1024)=Im
#pragma unroll
        for (int k = 0; k < 2; k++) {
            int j0 = jb + 2 * k;
            emitS(i0,        j0, are[k]);
            emitS(512 + i0,  j0, aim[k]);
            emitS(i1,        j0, bre[k]);
            emitS(512 + i1,  j0, bim[k]);
        }
    } else {
        // Bstk[m][kk] = [[Re, -Im],[Im, Re]] of T1 (m-major, 1024 wide)
#pragma unroll
        for (int k = 0; k < 2; k++) {
            int j0 = jb + 2 * k;
            emitB(i0,        j0,       are[k], false);
            emitB(i0,        512 + j0, aim[k], true);
            emitB(512 + i0,  j0,       aim[k], false);
            emitB(512 + i0,  512 + j0, are[k], false);
            emitB(i1,        j0,       bre[k], false);
            emitB(i1,        512 + j0, bim[k], true);
            emitB(512 + i1,  j0,       bim[k], false);
            emitB(512 + i1,  512 + j0, bre[k], false);
        }
    }
}

// ===========================================================================
// mma.sync fp16 primitives (shared by compose and final GEMM)
// ===========================================================================
__device__ __forceinline__ void ldmx4(uint32_t* r, uint32_t addr) {
    asm volatile("ldmatrix.sync.aligned.m8n8.x4.shared.b16 {%0,%1,%2,%3}, [%4];"
                 : "=r"(r[0]), "=r"(r[1]), "=r"(r[2]), "=r"(r[3]) : "r"(addr));
}
__device__ __forceinline__ void ldmx4t(uint32_t* r, uint32_t addr) {
    asm volatile("ldmatrix.sync.aligned.m8n8.x4.trans.shared.b16 {%0,%1,%2,%3}, [%4];"
                 : "=r"(r[0]), "=r"(r[1]), "=r"(r[2]), "=r"(r[3]) : "r"(addr));
}
__device__ __forceinline__ void mma_f16(float* c, const uint32_t* a, uint32_t b0, uint32_t b1) {
    asm volatile("mma.sync.aligned.m16n8k16.row.col.f32.f16.f16.f32 "
                 "{%0,%1,%2,%3}, {%4,%5,%6,%7}, {%8,%9}, {%0,%1,%2,%3};"
                 : "+f"(c[0]), "+f"(c[1]), "+f"(c[2]), "+f"(c[3])
                 : "r"(a[0]), "r"(a[1]), "r"(a[2]), "r"(a[3]), "r"(b0), "r"(b1));
}

// ===========================================================================
// Kernel 3: compose GEMM. g_G_f32[1024x512] = Bstk[1024x1024] @ Sstk[1024x512]
// hi/lo 3-pass (Bh@Sh + Bh@Sl + Bl@Sh), fp32 accum, epilogue -> g_G fp16.
// CTA 128x128, BK=32, 96 stages, grid (4,8).
// ===========================================================================
__global__ __launch_bounds__(256) void compose_gemm() {
    __shared__ __align__(1024) char raw[3 * 16384];
    uint32_t sbase = smem_u32(raw);

    int tid = threadIdx.x;
    int lane = tid & 31, wid = tid >> 5;
    int wm = wid & 3, wn = wid >> 2;
    int bm = blockIdx.y * 128, bn = blockIdx.x * 128;

    auto issue = [&](int st, int buf) {
        int p = st >> 5;
        int kblk = (st & 31) << 5;
        const __half* Ap = (p == 2) ? g_Bl : g_Bh;
        const __half* Bp = (p == 1) ? g_Sl : g_Sh;
        uint32_t base = sbase + buf * 16384;
#pragma unroll
        for (int h = 0; h < 2; h++) {
            int cA = tid + h * 256;
            int row = cA >> 2, kc = cA & 3;
            uint32_t dA = base + row * 64 + ((kc ^ ((row >> 1) & 3)) << 4);
            const __half* sA = Ap + (size_t)(bm + row) * 1024 + kblk + kc * 8;
            asm volatile("cp.async.cg.shared.global [%0], [%1], 16;" :: "r"(dA), "l"(sA));
            int cB = tid + h * 256;
            int k = cB >> 4, nch = cB & 15;
            uint32_t dB = base + 8192 + k * 256 + ((nch ^ (k & 7)) << 4);
            const __half* sB = Bp + (size_t)(kblk + k) * 512 + bn + nch * 8;
            asm volatile("cp.async.cg.shared.global [%0], [%1], 16;" :: "r"(dB), "l"(sB));
        }
        asm volatile("cp.async.commit_group;" ::: "memory");
    };

    int grp = lane >> 3, lrow = lane & 7;
    int g1 = grp & 1, g2 = grp >> 1;
    int arow = wm * 32 + g1 * 8 + lrow;
    uint32_t aBase = arow * 64 + ((g2 ^ (lrow >> 1)) << 4);
    int bk = g1 * 8 + lrow;
    uint32_t bBase = 8192 + bk * 256 + wn * 128 + ((g2 ^ lrow) << 4);

    float acc[2][8][4];
#pragma unroll
    for (int mt = 0; mt < 2; mt++)
#pragma unroll
        for (int nj = 0; nj < 8; nj++)
#pragma unroll
            for (int q = 0; q < 4; q++) acc[mt][nj][q] = 0.f;

    issue(0, 0);
    issue(1, 1);

#pragma unroll 1
    for (int st = 0; st < 96; st++) {
        int buf = st % 3;
        if (st < 95) asm volatile("cp.async.wait_group 1;" ::: "memory");
        else         asm volatile("cp.async.wait_group 0;" ::: "memory");
        __syncthreads();
        if (st + 2 < 96) issue(st + 2, (st + 2) % 3);

        uint32_t stage = sbase + buf * 16384;
#pragma unroll
        for (int s = 0; s < 2; s++) {
            uint32_t a[2][4];
            ldmx4(a[0], (stage + aBase) ^ (s << 5));
            ldmx4(a[1], (stage + aBase + 16 * 64) ^ (s << 5));
#pragma unroll
            for (int j2 = 0; j2 < 4; j2++) {
                uint32_t b[4];
                ldmx4t(b, (stage + bBase + (s << 12)) ^ (j2 << 5));
#pragma unroll
                for (int mt = 0; mt < 2; mt++) {
                    mma_f16(acc[mt][2 * j2],     a[mt], b[0], b[1]);
                    mma_f16(acc[mt][2 * j2 + 1], a[mt], b[2], b[3]);
                }
            }
        }
    }

    // epilogue: write final A as fp16 into g_G (m-major, 512 wide)
    int mrow = bm + wm * 32 + (lane >> 2);
    int ncol = bn + wn * 64 + (lane & 3) * 2;
#pragma unroll
    for (int mt = 0; mt < 2; mt++) {
#pragma unroll
        for (int nj = 0; nj < 8; nj++) {
            __half2 v01, v23;
            v01.x = __float2half_rn(acc[mt][nj][0]);
            v01.y = __float2half_rn(acc[mt][nj][1]);
            v23.x = __float2half_rn(acc[mt][nj][2]);
            v23.y = __float2half_rn(acc[mt][nj][3]);
            *reinterpret_cast<__half2*>(&g_G[(size_t)(mrow + mt * 16) * 512 + ncol + nj * 8])     = v01;
            *reinterpret_cast<__half2*>(&g_G[(size_t)(mrow + mt * 16 + 8) * 512 + ncol + nj * 8]) = v23;
        }
    }
}

// ===========================================================================
// Kernel 4: final fp16 GEMM (unchanged from the 143.4us winner).
// out[1024][8192] = G @ X, fp32 acc. CTA 128x128, BK=32, 16 stages.
// ===========================================================================
__global__ __launch_bounds__(256, 2) void mma_gemm(float* __restrict__ out) {
    __shared__ __align__(1024) char raw[3 * 16384];
    uint32_t sbase = smem_u32(raw);

    int tid = threadIdx.x;
    int lane = tid & 31, wid = tid >> 5;
    int wm = wid & 3, wn = wid >> 2;
    int bm = blockIdx.y * 128, bn = blockIdx.x * 128;

    auto issue = [&](int st, int buf) {
        int kblk = st << 5;
        uint32_t base = sbase + buf * 16384;
#pragma unroll
        for (int h = 0; h < 2; h++) {
            int cA = tid + h * 256;
            int row = cA >> 2, kc = cA & 3;
            uint32_t dA = base + row * 64 + ((kc ^ ((row >> 1) & 3)) << 4);
            const __half* sA = g_G + (size_t)(bm + row) * 512 + kblk + kc * 8;
            asm volatile("cp.async.cg.shared.global [%0], [%1], 16;" :: "r"(dA), "l"(sA));
            int cB = tid + h * 256;
            int k = cB >> 4, nch = cB & 15;
            uint32_t dB = base + 8192 + k * 256 + ((nch ^ (k & 7)) << 4);
            const __half* sB = g_X + (size_t)(kblk + k) * 8192 + bn + nch * 8;
            asm volatile("cp.async.cg.shared.global [%0], [%1], 16;" :: "r"(dB), "l"(sB));
        }
        asm volatile("cp.async.commit_group;" ::: "memory");
    };

    int grp = lane >> 3, lrow = lane & 7;
    int g1 = grp & 1, g2 = grp >> 1;
    int arow = wm * 32 + g1 * 8 + lrow;
    uint32_t aBase = arow * 64 + ((g2 ^ (lrow >> 1)) << 4);
    int bk = g1 * 8 + lrow;
    uint32_t bBase = 8192 + bk * 256 + wn * 128 + ((g2 ^ lrow) << 4);

    float acc[2][8][4];
#pragma unroll
    for (int mt = 0; mt < 2; mt++)
#pragma unroll
        for (int nj = 0; nj < 8; nj++)
#pragma unroll
            for (int q = 0; q < 4; q++) acc[mt][nj][q] = 0.f;

    issue(0, 0);
    issue(1, 1);

#pragma unroll 1
    for (int st = 0; st < 16; st++) {
        int buf = st % 3;
        if (st < 15) asm volatile("cp.async.wait_group 1;" ::: "memory");
        else         asm volatile("cp.async.wait_group 0;" ::: "memory");
        __syncthreads();
        if (st + 2 < 16) issue(st + 2, (st + 2) % 3);

        uint32_t stage = sbase + buf * 16384;
#pragma unroll
        for (int s = 0; s < 2; s++) {
            uint32_t a[2][4];
            ldmx4(a[0], (stage + aBase) ^ (s << 5));
            ldmx4(a[1], (stage + aBase + 16 * 64) ^ (s << 5));
#pragma unroll
            for (int j2 = 0; j2 < 4; j2++) {
                uint32_t b[4];
                ldmx4t(b, (stage + bBase + (s << 12)) ^ (j2 << 5));
#pragma unroll
                for (int mt = 0; mt < 2; mt++) {
                    mma_f16(acc[mt][2 * j2],     a[mt], b[0], b[1]);
                    mma_f16(acc[mt][2 * j2 + 1], a[mt], b[2], b[3]);
                }
            }
        }
    }

    int mrow = bm + wm * 32 + (lane >> 2);
    int ncol = bn + wn * 64 + (lane & 3) * 2;
#pragma unroll
    for (int mt = 0; mt < 2; mt++) {
#pragma unroll
        for (int nj = 0; nj < 8; nj++) {
            float* o = out + (size_t)(mrow + mt * 16) * 8192 + ncol + nj * 8;
            *reinterpret_cast<float2*>(o)             = make_float2(acc[mt][nj][0], acc[mt][nj][1]);
            *reinterpret_cast<float2*>(o + 8 * 8192)  = make_float2(acc[mt][nj][2], acc[mt][nj][3]);
        }
    }
}

// ===========================================================================
// Launch
// ===========================================================================
extern "C" void kernel_launch(void* const* d_in, const int* in_sizes, int n_in,
                              void* d_out, int out_size) {
    const float* x      = (const float*)d_in[0];
    const float* thetas = (const float*)d_in[1];
    const float* phis   = (const float*)d_in[2];
    const float* gammas = (const float*)d_in[3];
    const float* bse    = (const float*)d_in[4];
    const float* lse    = (const float*)d_in[5];
    (void)in_sizes; (void)n_in; (void)out_size;

    prep_kernel<<<4096 + 512, 256>>>((const float4*)x, thetas, phis, bse, lse);
    propagate<<<256, 256>>>(gammas);
    compose_gemm<<<dim3(4, 8), 256>>>();
    mma_gemm<<<dim3(64, 8), 256>>>((float*)d_out);
}

// round 16
// speedup vs baseline: 1.3626x; 1.2897x over previous
#include <cuda_runtime.h>
#include <cuda_fp16.h>
#include <cstdint>

#define N_WG   512
#define MPAIR  256
#define NCOL   512
#define N_NODE (NCOL * MPAIR)
#define BATCH  8192

// ===========================================================================
// Packed f32x2 helpers
// ===========================================================================
typedef unsigned long long F2;
__device__ __forceinline__ F2 pk(float lo, float hi) {
    F2 r; asm("mov.b64 %0, {%1, %2};" : "=l"(r) : "f"(lo), "f"(hi)); return r;
}
__device__ __forceinline__ void un2(F2 v, float& lo, float& hi) {
    asm("mov.b64 {%0, %1}, %2;" : "=f"(lo), "=f"(hi) : "l"(v));
}
__device__ __forceinline__ F2 splat(float a) { return pk(a, a); }
__device__ __forceinline__ F2 fma2(F2 a, F2 b, F2 c) {
    F2 d; asm("fma.rn.f32x2 %0, %1, %2, %3;" : "=l"(d) : "l"(a), "l"(b), "l"(c)); return d;
}
__device__ __forceinline__ F2 mul2(F2 a, F2 b) {
    F2 d; asm("mul.rn.f32x2 %0, %1, %2;" : "=l"(d) : "l"(a), "l"(b)); return d;
}
__device__ __forceinline__ float2 cmul(float2 a, float2 b) {
    return make_float2(a.x * b.x - a.y * b.y, a.x * b.y + a.y * b.x);
}
__device__ __forceinline__ float2 cadd(float2 a, float2 b) {
    return make_float2(a.x + b.x, a.y + b.y);
}
__device__ __forceinline__ uint32_t smem_u32(const void* p) {
    uint32_t a;
    asm("{ .reg .u64 t; cvta.to.shared.u64 t, %1; cvt.u32.u64 %0, t; }" : "=r"(a) : "l"(p));
    return a;
}

// ===========================================================================
// Static scratch
// ===========================================================================
__device__ float2 g_U00[N_NODE], g_U01[N_NODE], g_U10[N_NODE], g_U11[N_NODE];
// Final A matrix [Re;Im] m-major (1024 x 512), fp16 (input to final GEMM)
__device__ __align__(16) __half g_G[1024 * 512];
// X, [k][n] layout, fp16
__device__ __align__(16) __half g_X[512 * 8192];
// Segment-0 result S0 = T0*diag(e^ig), stacked [Re;Im]: 1024x512, fp16
__device__ __align__(16) __half g_S[1024 * 512];
// Segment-1 result T1 as Bstk = [[Re,-Im],[Im,Re]], m-major 1024x1024, fp16
__device__ __align__(16) __half g_B[1024 * 1024];
// Split-K partial sums for compose: 4 slabs of 1024x512 fp32
__device__ __align__(16) float g_Gp[4][1024 * 512];

// ===========================================================================
// Kernel 1 (fused): blocks [0,4096) convert X fp32->fp16;
//                   blocks [4096,4608) build per-node 2x2 U.
// ===========================================================================
__global__ __launch_bounds__(256) void prep_kernel(
        const float4* __restrict__ X4,
        const float* __restrict__ th, const float* __restrict__ ph,
        const float* __restrict__ bse, const float* __restrict__ lse) {
    if (blockIdx.x < 4096) {
        int i = blockIdx.x * 256 + threadIdx.x;
        float4 v = X4[i];
        __half2 h0, h1;
        h0.x = __float2half_rn(v.x); h0.y = __float2half_rn(v.y);
        h1.x = __float2half_rn(v.z); h1.y = __float2half_rn(v.w);
        __half2* X2 = reinterpret_cast<__half2*>(g_X);
        X2[2 * i] = h0; X2[2 * i + 1] = h1;
        return;
    }
    int idx = (blockIdx.x - 4096) * 256 + threadIdx.x;
    int c = idx >> 8;
    int p = idx & 255;
    bool msk = ((c & 1) == 0) || (p < MPAIR - 1);

    float2 U00 = {1.f, 0.f}, U01 = {0.f, 0.f}, U10 = {0.f, 0.f}, U11 = {1.f, 0.f};
    if (msk) {
        float theta = th[idx], phi = ph[idx];
        float e0 = bse[2 * idx], e1 = bse[2 * idx + 1];
        float l0 = lse[2 * idx], l1 = lse[2 * idx + 1];
        const float KL = 0.11512925464970229f;  // ln(10)/20
        float ins0 = expf(l0 * KL), ins1 = expf(l1 * KL);
        const float PI4 = 0.7853981633974483f;
        float s0, c0, s1, c1;
        sincosf(PI4 + e0, &s0, &c0);
        sincosf(PI4 + e1, &s1, &c1);
        float2 EL, ET;
        sincosf(phi, &EL.y, &EL.x);
        sincosf(theta, &ET.y, &ET.x);
        float2 L11 = {ins0 * s0, 0.f}, L12 = {0.f, ins0 * c0}, L21 = {0.f, c0}, L22 = {s0, 0.f};
        float2 R11 = {ins1 * s1, 0.f}, R12 = {0.f, ins1 * c1}, R21 = {0.f, c1}, R22 = {s1, 0.f};
        float2 M00 = cmul(L11, cmul(EL, ET));
        float2 M10 = cmul(L12, EL);
        float2 M01 = cmul(L21, ET);
        float2 M11 = L22;
        U00 = cadd(cmul(R11, M00), cmul(R21, M10));
        U01 = cadd(cmul(R11, M01), cmul(R21, M11));
        U10 = cadd(cmul(R12, M00), cmul(R22, M10));
        U11 = cadd(cmul(R12, M01), cmul(R22, M11));
    }
    g_U00[idx] = U00; g_U01[idx] = U01; g_U10[idx] = U10; g_U11[idx] = U11;
}

// ===========================================================================
// Kernel 2: segmented propagation (proven in round 15). 2 segments x 256 cols.
// CTAs [0,128): segment 0, seed diag(e^ig)  -> writes Sstk fp16
// CTAs [128,256): segment 1, seed identity  -> writes Bstk fp16
// ===========================================================================
__device__ __forceinline__ void apply2(const F2* S, F2& tr, F2& ti, F2& br, F2& bi) {
    F2 ntr = fma2(S[5],  bi, fma2(S[3], br, fma2(S[2], ti, mul2(S[0], tr))));
    F2 nti = fma2(S[4],  br, fma2(S[3], bi, fma2(S[1], tr, mul2(S[0], ti))));
    F2 nbr = fma2(S[11], bi, fma2(S[9], br, fma2(S[8], ti, mul2(S[6], tr))));
    F2 nbi = fma2(S[10], br, fma2(S[9], bi, fma2(S[7], tr, mul2(S[6], ti))));
    tr = ntr; ti = nti; br = nbr; bi = nbi;
}

__device__ __forceinline__ void emitS(int row, int col, F2 v) {
    float x, y; un2(v, x, y);
    __half2 H; H.x = __float2half_rn(x); H.y = __float2half_rn(y);
    *reinterpret_cast<__half2*>(&g_S[(size_t)row * 512 + col]) = H;
}
__device__ __forceinline__ void emitB(int row, int col, F2 v, bool neg) {
    float x, y; un2(v, x, y);
    if (neg) { x = -x; y = -y; }
    __half2 H; H.x = __float2half_rn(x); H.y = __float2half_rn(y);
    *reinterpret_cast<__half2*>(&g_B[(size_t)row * 1024 + col]) = H;
}

__global__ __launch_bounds__(256, 2) void propagate(const float* __restrict__ gammas) {
    int r   = threadIdx.x;
    int bid = blockIdx.x;
    int seg = bid >> 7;
    int jb  = (bid & 127) * 4;
    int cbase = seg << 8;

    int i0 = 2 * r, i1 = 2 * r + 1;
    int lane = r & 31, w = r >> 5;

    float sg0 = 0.f, cg0 = 1.f, sg1 = 0.f, cg1 = 1.f;
    if (seg == 0) {
        sincosf(gammas[i0], &sg0, &cg0);
        sincosf(gammas[i1], &sg1, &cg1);
    }

    F2 are[2], aim[2], bre[2], bim[2];
#pragma unroll
    for (int k = 0; k < 2; k++) {
        int j0 = jb + 2 * k, j1 = j0 + 1;
        are[k] = pk(i0 == j0 ? cg0 : 0.f, i0 == j1 ? cg0 : 0.f);
        aim[k] = pk(i0 == j0 ? sg0 : 0.f, i0 == j1 ? sg0 : 0.f);
        bre[k] = pk(i1 == j0 ? cg1 : 0.f, i1 == j1 ? cg1 : 0.f);
        bim[k] = pk(i1 == j0 ? sg1 : 0.f, i1 == j1 ? sg1 : 0.f);
    }

    __shared__ F2 sEA[8][4];
    __shared__ F2 sEB[8][4];

    int ub = (cbase << 8) + r;
    float2 u00 = g_U00[ub], u01 = g_U01[ub], u10 = g_U10[ub], u11 = g_U11[ub];

    for (int c = 0; c < 256; c++) {
        float2 p00, p01, p10, p11;
        if (c + 1 < 256) {
            int nidx = ((cbase + c + 1) << 8) + r;
            p00 = g_U00[nidx]; p01 = g_U01[nidx]; p10 = g_U10[nidx]; p11 = g_U11[nidx];
        }
        F2 S[12] = {
            splat(u00.x), splat(u00.y), splat(-u00.y),
            splat(u01.x), splat(u01.y), splat(-u01.y),
            splat(u10.x), splat(u10.y), splat(-u10.y),
            splat(u11.x), splat(u11.y), splat(-u11.y)
        };
        if ((c & 1) == 0) {
#pragma unroll
            for (int k = 0; k < 2; k++)
                apply2(S, are[k], aim[k], bre[k], bim[k]);
        } else {
            F2 nar[2], nai[2];
#pragma unroll
            for (int k = 0; k < 2; k++) {
                nar[k] = __shfl_down_sync(0xffffffffu, are[k], 1);
                nai[k] = __shfl_down_sync(0xffffffffu, aim[k], 1);
            }
            if (lane == 0 && r > 0) {
                sEA[w][0] = are[0]; sEA[w][1] = are[1];
                sEA[w][2] = aim[0]; sEA[w][3] = aim[1];
            }
            __syncthreads();
            if (lane == 31 && r < 255) {
                nar[0] = sEA[w + 1][0]; nar[1] = sEA[w + 1][1];
                nai[0] = sEA[w + 1][2]; nai[1] = sEA[w + 1][3];
            }
            if (r < 255) {
#pragma unroll
                for (int k = 0; k < 2; k++)
                    apply2(S, bre[k], bim[k], nar[k], nai[k]);
            }
            F2 up0 = __shfl_up_sync(0xffffffffu, nar[0], 1);
            F2 up1 = __shfl_up_sync(0xffffffffu, nar[1], 1);
            F2 up2 = __shfl_up_sync(0xffffffffu, nai[0], 1);
            F2 up3 = __shfl_up_sync(0xffffffffu, nai[1], 1);
            if (lane == 31 && r < 255) {
                sEB[w + 1][0] = nar[0]; sEB[w + 1][1] = nar[1];
                sEB[w + 1][2] = nai[0]; sEB[w + 1][3] = nai[1];
            }
            __syncthreads();
            if (r > 0) {
                if (lane == 0) {
                    are[0] = sEB[w][0]; are[1] = sEB[w][1];
                    aim[0] = sEB[w][2]; aim[1] = sEB[w][3];
                } else {
                    are[0] = up0; are[1] = up1; aim[0] = up2; aim[1] = up3;
                }
            }
        }
        u00 = p00; u01 = p01; u10 = p10; u11 = p11;
    }

    if (seg == 0) {
#pragma unroll
        for (int k = 0; k < 2; k++) {
            int j0 = jb + 2 * k;
            emitS(i0,        j0, are[k]);
            emitS(512 + i0,  j0, aim[k]);
            emitS(i1,        j0, bre[k]);
            emitS(512 + i1,  j0, bim[k]);
        }
    } else {
#pragma unroll
        for (int k = 0; k < 2; k++) {
            int j0 = jb + 2 * k;
            emitB(i0,        j0,       are[k], false);
            emitB(i0,        512 + j0, aim[k], true);
            emitB(512 + i0,  j0,       aim[k], false);
            emitB(512 + i0,  512 + j0, are[k], false);
            emitB(i1,        j0,       bre[k], false);
            emitB(i1,        512 + j0, bim[k], true);
            emitB(512 + i1,  j0,       bim[k], false);
            emitB(512 + i1,  512 + j0, bre[k], false);
        }
    }
}

// ===========================================================================
// mma.sync fp16 primitives
// ===========================================================================
__device__ __forceinline__ void ldmx4(uint32_t* r, uint32_t addr) {
    asm volatile("ldmatrix.sync.aligned.m8n8.x4.shared.b16 {%0,%1,%2,%3}, [%4];"
                 : "=r"(r[0]), "=r"(r[1]), "=r"(r[2]), "=r"(r[3]) : "r"(addr));
}
__device__ __forceinline__ void ldmx4t(uint32_t* r, uint32_t addr) {
    asm volatile("ldmatrix.sync.aligned.m8n8.x4.trans.shared.b16 {%0,%1,%2,%3}, [%4];"
                 : "=r"(r[0]), "=r"(r[1]), "=r"(r[2]), "=r"(r[3]) : "r"(addr));
}
__device__ __forceinline__ void mma_f16(float* c, const uint32_t* a, uint32_t b0, uint32_t b1) {
    asm volatile("mma.sync.aligned.m16n8k16.row.col.f32.f16.f16.f32 "
                 "{%0,%1,%2,%3}, {%4,%5,%6,%7}, {%8,%9}, {%0,%1,%2,%3};"
                 : "+f"(c[0]), "+f"(c[1]), "+f"(c[2]), "+f"(c[3])
                 : "r"(a[0]), "r"(a[1]), "r"(a[2]), "r"(a[3]), "r"(b0), "r"(b1));
}

// ===========================================================================
// Kernel 3: compose GEMM, split-K. grid (4, 8, 4): z = K-chunk of 256.
// g_Gp[z][1024x512] = Bstk[:, z*256:(z+1)*256] @ Sstk[z*256:(z+1)*256, :]
// Single fp16 pass, fp32 accum. CTA 128x128, BK=32, 8 stages.
// ===========================================================================
__global__ __launch_bounds__(256) void compose_gemm() {
    __shared__ __align__(1024) char raw[3 * 16384];
    uint32_t sbase = smem_u32(raw);

    int tid = threadIdx.x;
    int lane = tid & 31, wid = tid >> 5;
    int wm = wid & 3, wn = wid >> 2;
    int bm = blockIdx.y * 128, bn = blockIdx.x * 128;
    int kbase = blockIdx.z * 256;
    float* outp = g_Gp[blockIdx.z];

    auto issue = [&](int st, int buf) {
        int kblk = kbase + (st << 5);
        uint32_t base = sbase + buf * 16384;
#pragma unroll
        for (int h = 0; h < 2; h++) {
            int cA = tid + h * 256;
            int row = cA >> 2, kc = cA & 3;
            uint32_t dA = base + row * 64 + ((kc ^ ((row >> 1) & 3)) << 4);
            const __half* sA = g_B + (size_t)(bm + row) * 1024 + kblk + kc * 8;
            asm volatile("cp.async.cg.shared.global [%0], [%1], 16;" :: "r"(dA), "l"(sA));
            int cB = tid + h * 256;
            int k = cB >> 4, nch = cB & 15;
            uint32_t dB = base + 8192 + k * 256 + ((nch ^ (k & 7)) << 4);
            const __half* sB = g_S + (size_t)(kblk + k) * 512 + bn + nch * 8;
            asm volatile("cp.async.cg.shared.global [%0], [%1], 16;" :: "r"(dB), "l"(sB));
        }
        asm volatile("cp.async.commit_group;" ::: "memory");
    };

    int grp = lane >> 3, lrow = lane & 7;
    int g1 = grp & 1, g2 = grp >> 1;
    int arow = wm * 32 + g1 * 8 + lrow;
    uint32_t aBase = arow * 64 + ((g2 ^ (lrow >> 1)) << 4);
    int bk = g1 * 8 + lrow;
    uint32_t bBase = 8192 + bk * 256 + wn * 128 + ((g2 ^ lrow) << 4);

    float acc[2][8][4];
#pragma unroll
    for (int mt = 0; mt < 2; mt++)
#pragma unroll
        for (int nj = 0; nj < 8; nj++)
#pragma unroll
            for (int q = 0; q < 4; q++) acc[mt][nj][q] = 0.f;

    issue(0, 0);
    issue(1, 1);

#pragma unroll 1
    for (int st = 0; st < 8; st++) {
        int buf = st % 3;
        if (st < 7) asm volatile("cp.async.wait_group 1;" ::: "memory");
        else        asm volatile("cp.async.wait_group 0;" ::: "memory");
        __syncthreads();
        if (st + 2 < 8) issue(st + 2, (st + 2) % 3);

        uint32_t stage = sbase + buf * 16384;
#pragma unroll
        for (int s = 0; s < 2; s++) {
            uint32_t a[2][4];
            ldmx4(a[0], (stage + aBase) ^ (s << 5));
            ldmx4(a[1], (stage + aBase + 16 * 64) ^ (s << 5));
#pragma unroll
            for (int j2 = 0; j2 < 4; j2++) {
                uint32_t b[4];
                ldmx4t(b, (stage + bBase + (s << 12)) ^ (j2 << 5));
#pragma unroll
                for (int mt = 0; mt < 2; mt++) {
                    mma_f16(acc[mt][2 * j2],     a[mt], b[0], b[1]);
                    mma_f16(acc[mt][2 * j2 + 1], a[mt], b[2], b[3]);
                }
            }
        }
    }

    int mrow = bm + wm * 32 + (lane >> 2);
    int ncol = bn + wn * 64 + (lane & 3) * 2;
#pragma unroll
    for (int mt = 0; mt < 2; mt++) {
#pragma unroll
        for (int nj = 0; nj < 8; nj++) {
            float* o = outp + (size_t)(mrow + mt * 16) * 512 + ncol + nj * 8;
            *reinterpret_cast<float2*>(o)           = make_float2(acc[mt][nj][0], acc[mt][nj][1]);
            *reinterpret_cast<float2*>(o + 8 * 512) = make_float2(acc[mt][nj][2], acc[mt][nj][3]);
        }
    }
}

// ===========================================================================
// Kernel 3b: combine split-K partials -> g_G fp16. 262144 threads x 2 elems.
// ===========================================================================
__global__ __launch_bounds__(256) void combine_kernel() {
    int i = (blockIdx.x * 256 + threadIdx.x) * 2;
    float a0 = g_Gp[0][i] + g_Gp[1][i] + g_Gp[2][i] + g_Gp[3][i];
    float a1 = g_Gp[0][i + 1] + g_Gp[1][i + 1] + g_Gp[2][i + 1] + g_Gp[3][i + 1];
    __half2 h; h.x = __float2half_rn(a0); h.y = __float2half_rn(a1);
    *reinterpret_cast<__half2*>(&g_G[i]) = h;
}

// ===========================================================================
// Kernel 4: final fp16 GEMM (unchanged). out[1024][8192] = G @ X, fp32 acc.
// ===========================================================================
__global__ __launch_bounds__(256, 2) void mma_gemm(float* __restrict__ out) {
    __shared__ __align__(1024) char raw[3 * 16384];
    uint32_t sbase = smem_u32(raw);

    int tid = threadIdx.x;
    int lane = tid & 31, wid = tid >> 5;
    int wm = wid & 3, wn = wid >> 2;
    int bm = blockIdx.y * 128, bn = blockIdx.x * 128;

    auto issue = [&](int st, int buf) {
        int kblk = st << 5;
        uint32_t base = sbase + buf * 16384;
#pragma unroll
        for (int h = 0; h < 2; h++) {
            int cA = tid + h * 256;
            int row = cA >> 2, kc = cA & 3;
            uint32_t dA = base + row * 64 + ((kc ^ ((row >> 1) & 3)) << 4);
            const __half* sA = g_G + (size_t)(bm + row) * 512 + kblk + kc * 8;
            asm volatile("cp.async.cg.shared.global [%0], [%1], 16;" :: "r"(dA), "l"(sA));
            int cB = tid + h * 256;
            int k = cB >> 4, nch = cB & 15;
            uint32_t dB = base + 8192 + k * 256 + ((nch ^ (k & 7)) << 4);
            const __half* sB = g_X + (size_t)(kblk + k) * 8192 + bn + nch * 8;
            asm volatile("cp.async.cg.shared.global [%0], [%1], 16;" :: "r"(dB), "l"(sB));
        }
        asm volatile("cp.async.commit_group;" ::: "memory");
    };

    int grp = lane >> 3, lrow = lane & 7;
    int g1 = grp & 1, g2 = grp >> 1;
    int arow = wm * 32 + g1 * 8 + lrow;
    uint32_t aBase = arow * 64 + ((g2 ^ (lrow >> 1)) << 4);
    int bk = g1 * 8 + lrow;
    uint32_t bBase = 8192 + bk * 256 + wn * 128 + ((g2 ^ lrow) << 4);

    float acc[2][8][4];
#pragma unroll
    for (int mt = 0; mt < 2; mt++)
#pragma unroll
        for (int nj = 0; nj < 8; nj++)
#pragma unroll
            for (int q = 0; q < 4; q++) acc[mt][nj][q] = 0.f;

    issue(0, 0);
    issue(1, 1);

#pragma unroll 1
    for (int st = 0; st < 16; st++) {
        int buf = st % 3;
        if (st < 15) asm volatile("cp.async.wait_group 1;" ::: "memory");
        else         asm volatile("cp.async.wait_group 0;" ::: "memory");
        __syncthreads();
        if (st + 2 < 16) issue(st + 2, (st + 2) % 3);

        uint32_t stage = sbase + buf * 16384;
#pragma unroll
        for (int s = 0; s < 2; s++) {
            uint32_t a[2][4];
            ldmx4(a[0], (stage + aBase) ^ (s << 5));
            ldmx4(a[1], (stage + aBase + 16 * 64) ^ (s << 5));
#pragma unroll
            for (int j2 = 0; j2 < 4; j2++) {
                uint32_t b[4];
                ldmx4t(b, (stage + bBase + (s << 12)) ^ (j2 << 5));
#pragma unroll
                for (int mt = 0; mt < 2; mt++) {
                    mma_f16(acc[mt][2 * j2],     a[mt], b[0], b[1]);
                    mma_f16(acc[mt][2 * j2 + 1], a[mt], b[2], b[3]);
                }
            }
        }
    }

    int mrow = bm + wm * 32 + (lane >> 2);
    int ncol = bn + wn * 64 + (lane & 3) * 2;
#pragma unroll
    for (int mt = 0; mt < 2; mt++) {
#pragma unroll
        for (int nj = 0; nj < 8; nj++) {
            float* o = out + (size_t)(mrow + mt * 16) * 8192 + ncol + nj * 8;
            *reinterpret_cast<float2*>(o)             = make_float2(acc[mt][nj][0], acc[mt][nj][1]);
            *reinterpret_cast<float2*>(o + 8 * 8192)  = make_float2(acc[mt][nj][2], acc[mt][nj][3]);
        }
    }
}

// ===========================================================================
// Launch
// ===========================================================================
extern "C" void kernel_launch(void* const* d_in, const int* in_sizes, int n_in,
                              void* d_out, int out_size) {
    const float* x      = (const float*)d_in[0];
    const float* thetas = (const float*)d_in[1];
    const float* phis   = (const float*)d_in[2];
    const float* gammas = (const float*)d_in[3];
    const float* bse    = (const float*)d_in[4];
    const float* lse    = (const float*)d_in[5];
    (void)in_sizes; (void)n_in; (void)out_size;

    prep_kernel<<<4096 + 512, 256>>>((const float4*)x, thetas, phis, bse, lse);
    propagate<<<256, 256>>>(gammas);
    compose_gemm<<<dim3(4, 8, 4), 256>>>();
    combine_kernel<<<1024, 256>>>();
    mma_gemm<<<dim3(64, 8), 256>>>((float*)d_out);
}